// round 3
// baseline (speedup 1.0000x reference)
#include <cuda_runtime.h>
#include <cuda_bf16.h>

// ---------------------------------------------------------------------------
// Problem shape (fixed):
//   x:    [4, 2048, 1024]  -> rows M = 8192, K = 1024
//   Wqkv: [1024, 3072], bqkv [3072]
//   Wout: [1024, 1024], bout [1024]
//   16 heads, head_size 64, causal softmax attention, fp32 out [8192,1024]
// ---------------------------------------------------------------------------

#define M_ROWS 8192
#define N_EMB  1024
#define N_QKV  3072
#define SEQ_T  2048
#define NHEAD  16
#define HS     64

// Scratch (allocation-free rule: __device__ globals)
__device__ float g_qkv [ (size_t)M_ROWS * N_QKV ];   // 96 MB
__device__ float g_attn[ (size_t)M_ROWS * N_EMB ];   // 32 MB

// ---------------------------------------------------------------------------
// Tiled fp32 GEMM + bias:  C[M,N] = A[M,K] @ W[K,N] + bias[N]
// BM=BN=128, BK=16, 256 threads, 8x8 per-thread micro-tile.
// ---------------------------------------------------------------------------
__global__ __launch_bounds__(256)
void sgemm_bias(const float* __restrict__ A, const float* __restrict__ W,
                const float* __restrict__ bias, float* __restrict__ C,
                int M, int N, int K) {
    const int BM = 128, BN = 128, BK = 16, TM = 8, TN = 8;
    __shared__ float As[BK][BM];   // A tile, transposed (k-major)
    __shared__ float Ws[BK][BN];

    int tid = threadIdx.x;                  // 0..255
    int bm  = blockIdx.y * BM;
    int bn  = blockIdx.x * BN;
    int trow = (tid / 16) * TM;             // 0,8,...,120
    int tcol = (tid % 16) * TN;             // 0,8,...,120

    float acc[TM][TN];
    #pragma unroll
    for (int i = 0; i < TM; i++)
        #pragma unroll
        for (int j = 0; j < TN; j++) acc[i][j] = 0.f;

    for (int k0 = 0; k0 < K; k0 += BK) {
        // Load A tile: 128 rows x 16 cols = 512 float4; 2 per thread.
        #pragma unroll
        for (int i = 0; i < 2; i++) {
            int v = tid + i * 256;          // 0..511
            int r = v >> 2;                 // row in tile 0..127
            int c = (v & 3) * 4;            // k-col 0,4,8,12
            float4 a = *reinterpret_cast<const float4*>(&A[(size_t)(bm + r) * K + k0 + c]);
            As[c + 0][r] = a.x; As[c + 1][r] = a.y;
            As[c + 2][r] = a.z; As[c + 3][r] = a.w;
        }
        // Load W tile: 16 rows x 128 cols = 512 float4; 2 per thread.
        #pragma unroll
        for (int i = 0; i < 2; i++) {
            int v = tid + i * 256;
            int r = v >> 5;                 // k-row 0..15
            int c = (v & 31) * 4;           // n-col
            *reinterpret_cast<float4*>(&Ws[r][c]) =
                *reinterpret_cast<const float4*>(&W[(size_t)(k0 + r) * N + bn + c]);
        }
        __syncthreads();

        #pragma unroll
        for (int kk = 0; kk < BK; kk++) {
            float ar[TM], wr[TN];
            *reinterpret_cast<float4*>(&ar[0]) = *reinterpret_cast<const float4*>(&As[kk][trow]);
            *reinterpret_cast<float4*>(&ar[4]) = *reinterpret_cast<const float4*>(&As[kk][trow + 4]);
            *reinterpret_cast<float4*>(&wr[0]) = *reinterpret_cast<const float4*>(&Ws[kk][tcol]);
            *reinterpret_cast<float4*>(&wr[4]) = *reinterpret_cast<const float4*>(&Ws[kk][tcol + 4]);
            #pragma unroll
            for (int i = 0; i < TM; i++)
                #pragma unroll
                for (int j = 0; j < TN; j++)
                    acc[i][j] += ar[i] * wr[j];
        }
        __syncthreads();
    }

    // Epilogue: bias + store
    #pragma unroll
    for (int i = 0; i < TM; i++) {
        #pragma unroll
        for (int j = 0; j < TN; j += 4) {
            float4 o;
            o.x = acc[i][j + 0] + bias[bn + tcol + j + 0];
            o.y = acc[i][j + 1] + bias[bn + tcol + j + 1];
            o.z = acc[i][j + 2] + bias[bn + tcol + j + 2];
            o.w = acc[i][j + 3] + bias[bn + tcol + j + 3];
            *reinterpret_cast<float4*>(&C[(size_t)(bm + trow + i) * N + bn + tcol + j]) = o;
        }
    }
}

// ---------------------------------------------------------------------------
// Causal flash attention, fp32. One thread = one query row.
// Block = 128 threads (128 query rows); grid = (T/128, B*NHEAD).
// K/V tiles of 64 keys staged in smem; all inner smem reads are broadcast.
// ---------------------------------------------------------------------------
__global__ __launch_bounds__(128, 2)
void attn_kernel(const float* __restrict__ qkv, float* __restrict__ out) {
    const float scale = 0.125f;             // 1/sqrt(64)
    int tid = threadIdx.x;
    int bh  = blockIdx.y;
    int b   = bh >> 4;
    int h   = bh & 15;
    int row = blockIdx.x * 128 + tid;       // query position in sequence

    const float* base = qkv + (size_t)b * SEQ_T * N_QKV;

    // Load q row into registers
    float q[HS];
    {
        const float* qp = base + (size_t)row * N_QKV + h * HS;
        #pragma unroll
        for (int d = 0; d < HS; d += 4) {
            float4 t4 = *reinterpret_cast<const float4*>(qp + d);
            q[d] = t4.x; q[d + 1] = t4.y; q[d + 2] = t4.z; q[d + 3] = t4.w;
        }
    }

    float m = -1e30f, l = 0.f;
    float acc[HS];
    #pragma unroll
    for (int d = 0; d < HS; d++) acc[d] = 0.f;

    __shared__ float Ks[64][HS];
    __shared__ float Vs[64][HS];

    int kmax = blockIdx.x * 128 + 127;      // last query row in this block

    for (int k0 = 0; k0 <= kmax; k0 += 64) {
        // Cooperative tile load: 64 keys x 64 dims = 1024 float4 each for K and V
        #pragma unroll
        for (int i = 0; i < 8; i++) {
            int v = tid + i * 128;          // 0..1023
            int j = v >> 4;                 // key in tile
            int d = (v & 15) * 4;
            const float* kp = base + (size_t)(k0 + j) * N_QKV + N_EMB  + h * HS + d;
            const float* vp = base + (size_t)(k0 + j) * N_QKV + 2*N_EMB + h * HS + d;
            *reinterpret_cast<float4*>(&Ks[j][d]) = *reinterpret_cast<const float4*>(kp);
            *reinterpret_cast<float4*>(&Vs[j][d]) = *reinterpret_cast<const float4*>(vp);
        }
        __syncthreads();

        int jend = row - k0 + 1;            // causal bound within tile
        if (jend > 64) jend = 64;
        for (int j = 0; j < jend; j++) {
            float s = 0.f;
            #pragma unroll
            for (int d = 0; d < HS; d++) s += q[d] * Ks[j][d];
            s *= scale;
            if (s <= m) {
                float p = __expf(s - m);
                l += p;
                #pragma unroll
                for (int d = 0; d < HS; d++) acc[d] += p * Vs[j][d];
            } else {
                // new running max: rescale history (rare path)
                float corr = __expf(m - s);
                l = l * corr + 1.f;
                #pragma unroll
                for (int d = 0; d < HS; d++) acc[d] = acc[d] * corr + Vs[j][d];
                m = s;
            }
        }
        __syncthreads();
    }

    float inv = 1.f / l;
    float* op = out + ((size_t)(b * SEQ_T + row)) * N_EMB + h * HS;
    #pragma unroll
    for (int d = 0; d < HS; d += 4) {
        float4 o;
        o.x = acc[d + 0] * inv; o.y = acc[d + 1] * inv;
        o.z = acc[d + 2] * inv; o.w = acc[d + 3] * inv;
        *reinterpret_cast<float4*>(op + d) = o;
    }
}

// ---------------------------------------------------------------------------
// Launch
// ---------------------------------------------------------------------------
extern "C" void kernel_launch(void* const* d_in, const int* in_sizes, int n_in,
                              void* d_out, int out_size) {
    const float* x    = (const float*)d_in[0];
    const float* Wqkv = (const float*)d_in[1];
    const float* bqkv = (const float*)d_in[2];
    const float* Wout = (const float*)d_in[3];
    const float* bout = (const float*)d_in[4];
    float* out = (float*)d_out;

    float *qkv, *attn;
    cudaGetSymbolAddress((void**)&qkv,  g_qkv);
    cudaGetSymbolAddress((void**)&attn, g_attn);

    // 1) QKV projection: [8192,1024] @ [1024,3072] + bqkv
    sgemm_bias<<<dim3(N_QKV / 128, M_ROWS / 128), 256>>>(x, Wqkv, bqkv, qkv,
                                                         M_ROWS, N_QKV, N_EMB);
    // 2) Causal attention -> [8192,1024] (already merged head layout)
    attn_kernel<<<dim3(SEQ_T / 128, 4 * NHEAD), 128>>>(qkv, attn);

    // 3) Output projection: [8192,1024] @ [1024,1024] + bout
    sgemm_bias<<<dim3(N_EMB / 128, M_ROWS / 128), 256>>>(attn, Wout, bout, out,
                                                         M_ROWS, N_EMB, N_EMB);
}

// round 7
// speedup vs baseline: 1.4507x; 1.4507x over previous
#include <cuda_runtime.h>
#include <cuda_bf16.h>
#include <cstdint>

// ---------------------------------------------------------------------------
// Attention block on GB300 (sm_103 target — tcgen05 unavailable in harness):
//   x [8192,1024] -> QKV GEMM (mma.sync split-bf16) -> fp32 flash attention
//   -> out GEMM (mma.sync split-bf16)
// ---------------------------------------------------------------------------

#define M_ROWS 8192
#define N_EMB  1024
#define N_QKV  3072
#define SEQ_T  2048
#define NHEAD  16
#define HS     64
#define KDIM   1024

// Scratch (__device__ globals per allocation-free rule)
__device__ float g_qkv [(size_t)M_ROWS * N_QKV];    // 96 MB
__device__ float g_attn[(size_t)M_ROWS * N_EMB];    // 32 MB
__device__ __nv_bfloat16 g_xhi[(size_t)M_ROWS * KDIM];
__device__ __nv_bfloat16 g_xlo[(size_t)M_ROWS * KDIM];
__device__ __nv_bfloat16 g_ahi[(size_t)M_ROWS * KDIM];
__device__ __nv_bfloat16 g_alo[(size_t)M_ROWS * KDIM];
__device__ __nv_bfloat16 g_wqhi[(size_t)N_QKV * KDIM];  // Wqkv^T split
__device__ __nv_bfloat16 g_wqlo[(size_t)N_QKV * KDIM];
__device__ __nv_bfloat16 g_wohi[(size_t)N_EMB * KDIM];  // Wout^T split
__device__ __nv_bfloat16 g_wolo[(size_t)N_EMB * KDIM];

// ---------------------------------------------------------------------------
// PTX helpers (sm_80-portable subset only: ldmatrix / mma.sync / cp.async)
// ---------------------------------------------------------------------------
__device__ __forceinline__ uint32_t smem_u32(const void* p) {
    uint32_t a;
    asm("{ .reg .u64 t; cvta.to.shared.u64 t, %1; cvt.u32.u64 %0, t; }"
        : "=r"(a) : "l"(p));
    return a;
}
__device__ __forceinline__ uint32_t swz(uint32_t o) { return o ^ ((o >> 3) & 0x70); }

__device__ __forceinline__ void cp16(uint32_t dst, const void* src) {
    asm volatile("cp.async.cg.shared.global [%0], [%1], 16;" :: "r"(dst), "l"(src));
}
__device__ __forceinline__ void cp_commit() {
    asm volatile("cp.async.commit_group;" ::: "memory");
}
__device__ __forceinline__ void cp_wait1() {
    asm volatile("cp.async.wait_group 1;" ::: "memory");
}
__device__ __forceinline__ void cp_wait0() {
    asm volatile("cp.async.wait_group 0;" ::: "memory");
}

__device__ __forceinline__ void ldsm4(uint32_t& r0, uint32_t& r1, uint32_t& r2,
                                      uint32_t& r3, uint32_t addr) {
    asm volatile("ldmatrix.sync.aligned.m8n8.x4.shared.b16 {%0,%1,%2,%3}, [%4];"
                 : "=r"(r0), "=r"(r1), "=r"(r2), "=r"(r3) : "r"(addr));
}

__device__ __forceinline__ void mma16816(float* d, uint32_t a0, uint32_t a1,
                                         uint32_t a2, uint32_t a3,
                                         uint32_t b0, uint32_t b1) {
    asm volatile(
        "mma.sync.aligned.m16n8k16.row.col.f32.bf16.bf16.f32 "
        "{%0,%1,%2,%3}, {%4,%5,%6,%7}, {%8,%9}, {%0,%1,%2,%3};"
        : "+f"(d[0]), "+f"(d[1]), "+f"(d[2]), "+f"(d[3])
        : "r"(a0), "r"(a1), "r"(a2), "r"(a3), "r"(b0), "r"(b1));
}

// ---------------------------------------------------------------------------
// HMMA split-bf16 GEMM:  C[M,N] = (Ahi+Alo)[M,K] @ (Bhi+Blo)[N,K]^T + bias
// Tile 128x128, K-chunks of 64, 8 warps (2Mx4N), warp tile 64x32.
// Terms: hi*hi + hi*lo + lo*hi (fp32 acc) -> ~1e-5 relative error.
// ---------------------------------------------------------------------------
#define G_TILE   16384           // one 128x64 bf16 tile (SW128, 128B rows)
#define G_STAGE  (4 * G_TILE)    // Ahi, Alo, Bhi, Blo
#define G_SMEM   (2 * G_STAGE)   // 128 KB

__device__ __forceinline__ void load_chunk(
    uint32_t stage, int k0,
    const __nv_bfloat16* __restrict__ Ahi, const __nv_bfloat16* __restrict__ Alo,
    const __nv_bfloat16* __restrict__ Bhi, const __nv_bfloat16* __restrict__ Blo,
    int bm, int bn, int tid) {
    const __nv_bfloat16* bases[4] = {Ahi, Alo, Bhi, Blo};
    #pragma unroll
    for (int tile = 0; tile < 4; tile++) {
        const __nv_bfloat16* base = bases[tile];
        int rowbase = (tile < 2) ? bm : bn;
        #pragma unroll
        for (int j = 0; j < 4; j++) {
            int p = tid + j * 256;           // 0..1023 piece within tile
            int row = p >> 3;                // 0..127
            int c16 = p & 7;                 // 16B chunk within 128B row
            const __nv_bfloat16* src =
                base + (size_t)(rowbase + row) * KDIM + k0 + c16 * 8;
            uint32_t dst = stage + tile * G_TILE + swz(row * 128 + c16 * 16);
            cp16(dst, src);
        }
    }
    cp_commit();
}

__global__ __launch_bounds__(256, 1)
void gemm_mma(const __nv_bfloat16* __restrict__ Ahi, const __nv_bfloat16* __restrict__ Alo,
              const __nv_bfloat16* __restrict__ Bhi, const __nv_bfloat16* __restrict__ Blo,
              const float* __restrict__ bias, float* __restrict__ C, int N) {
    extern __shared__ char smem[];
    uint32_t sb = smem_u32(smem);
    int tid  = threadIdx.x;
    int lane = tid & 31;
    int w    = tid >> 5;
    int bm = blockIdx.y * 128;
    int bn = blockIdx.x * 128;
    int wm = (w >> 2) * 64;      // warp M offset within tile
    int wn = (w & 3) * 32;       // warp N offset within tile

    float acc[4][4][4];          // [m16 tile][n8 tile][reg]
    #pragma unroll
    for (int i = 0; i < 4; i++)
        #pragma unroll
        for (int j = 0; j < 4; j++)
            #pragma unroll
            for (int r = 0; r < 4; r++) acc[i][j][r] = 0.f;

    uint32_t st[2] = {sb, sb + G_STAGE};

    // per-thread ldmatrix address components
    int a_row = wm + (lane & 15);            // A: lane -> row within warp M span
    int a_hi8 = (lane >> 4);                 // A: k-halves select (16B chunks)
    int b_row = wn + (lane & 7) + ((lane >> 4) << 3);  // B: n row
    int b_hi8 = (lane >> 3) & 1;             // B: k-halves select

    load_chunk(st[0], 0,  Ahi, Alo, Bhi, Blo, bm, bn, tid);
    load_chunk(st[1], 64, Ahi, Alo, Bhi, Blo, bm, bn, tid);

    #pragma unroll 1
    for (int c = 0; c < 16; c++) {
        uint32_t stage = st[c & 1];
        if (c < 15) cp_wait1(); else cp_wait0();
        __syncthreads();

        uint32_t tAh = stage;
        uint32_t tAl = stage + G_TILE;
        uint32_t tBh = stage + 2 * G_TILE;
        uint32_t tBl = stage + 3 * G_TILE;

        #pragma unroll
        for (int ks = 0; ks < 4; ks++) {
            uint32_t ah[4][4], al[4][4], bh[2][4], bl[2][4];
            uint32_t ac16 = (uint32_t)(ks * 2 + a_hi8) * 16;
            uint32_t bc16 = (uint32_t)(ks * 2 + b_hi8) * 16;
            #pragma unroll
            for (int mt = 0; mt < 4; mt++) {
                uint32_t off = swz((uint32_t)(a_row + mt * 16) * 128 + ac16);
                ldsm4(ah[mt][0], ah[mt][1], ah[mt][2], ah[mt][3], tAh + off);
                ldsm4(al[mt][0], al[mt][1], al[mt][2], al[mt][3], tAl + off);
            }
            #pragma unroll
            for (int nt = 0; nt < 2; nt++) {
                uint32_t off = swz((uint32_t)(b_row + nt * 16) * 128 + bc16);
                ldsm4(bh[nt][0], bh[nt][1], bh[nt][2], bh[nt][3], tBh + off);
                ldsm4(bl[nt][0], bl[nt][1], bl[nt][2], bl[nt][3], tBl + off);
            }
            #pragma unroll
            for (int mt = 0; mt < 4; mt++) {
                #pragma unroll
                for (int n8 = 0; n8 < 4; n8++) {
                    uint32_t b0h = bh[n8 >> 1][(n8 & 1) * 2];
                    uint32_t b1h = bh[n8 >> 1][(n8 & 1) * 2 + 1];
                    uint32_t b0l = bl[n8 >> 1][(n8 & 1) * 2];
                    uint32_t b1l = bl[n8 >> 1][(n8 & 1) * 2 + 1];
                    mma16816(acc[mt][n8], ah[mt][0], ah[mt][1], ah[mt][2], ah[mt][3], b0h, b1h);
                    mma16816(acc[mt][n8], ah[mt][0], ah[mt][1], ah[mt][2], ah[mt][3], b0l, b1l);
                    mma16816(acc[mt][n8], al[mt][0], al[mt][1], al[mt][2], al[mt][3], b0h, b1h);
                }
            }
        }
        __syncthreads();
        if (c + 2 < 16)
            load_chunk(stage, (c + 2) * 64, Ahi, Alo, Bhi, Blo, bm, bn, tid);
    }

    // Epilogue: mma d-frag mapping -> gmem + bias
    int tr = lane >> 2;          // 0..7
    int tc = (lane & 3) * 2;     // 0,2,4,6
    #pragma unroll
    for (int mt = 0; mt < 4; mt++) {
        #pragma unroll
        for (int n8 = 0; n8 < 4; n8++) {
            int row0 = bm + wm + mt * 16 + tr;
            int col  = bn + wn + n8 * 8 + tc;
            float b0 = bias[col], b1 = bias[col + 1];
            float* p0 = C + (size_t)row0 * N + col;
            p0[0] = acc[mt][n8][0] + b0;
            p0[1] = acc[mt][n8][1] + b1;
            float* p1 = C + (size_t)(row0 + 8) * N + col;
            p1[0] = acc[mt][n8][2] + b0;
            p1[1] = acc[mt][n8][3] + b1;
        }
    }
}

// ---------------------------------------------------------------------------
// fp32 -> bf16 hi/lo split (elementwise, float4)
// ---------------------------------------------------------------------------
__global__ void split_f32(const float* __restrict__ in, __nv_bfloat16* __restrict__ hi,
                          __nv_bfloat16* __restrict__ lo, int n4) {
    int i = blockIdx.x * blockDim.x + threadIdx.x;
    if (i >= n4) return;
    float4 v = reinterpret_cast<const float4*>(in)[i];
    float vv[4] = {v.x, v.y, v.z, v.w};
    __nv_bfloat162 h2[2], l2[2];
    #pragma unroll
    for (int j = 0; j < 4; j++) {
        __nv_bfloat16 h = __float2bfloat16(vv[j]);
        __nv_bfloat16 l = __float2bfloat16(vv[j] - __bfloat162float(h));
        ((__nv_bfloat16*)h2)[j] = h;
        ((__nv_bfloat16*)l2)[j] = l;
    }
    reinterpret_cast<__nv_bfloat162*>(hi)[i * 2 + 0] = h2[0];
    reinterpret_cast<__nv_bfloat162*>(hi)[i * 2 + 1] = h2[1];
    reinterpret_cast<__nv_bfloat162*>(lo)[i * 2 + 0] = l2[0];
    reinterpret_cast<__nv_bfloat162*>(lo)[i * 2 + 1] = l2[1];
}

// ---------------------------------------------------------------------------
// W [K,N] fp32 -> Wt hi/lo [N,K] bf16 (transpose + split)
// ---------------------------------------------------------------------------
__global__ void transpose_split(const float* __restrict__ W, __nv_bfloat16* __restrict__ hi,
                                __nv_bfloat16* __restrict__ lo, int K, int N) {
    __shared__ float t[32][33];
    int bn = blockIdx.x * 32, bk = blockIdx.y * 32;
    int tx = threadIdx.x, ty = threadIdx.y;   // 32 x 8
    #pragma unroll
    for (int r = 0; r < 32; r += 8)
        t[ty + r][tx] = W[(size_t)(bk + ty + r) * N + bn + tx];
    __syncthreads();
    #pragma unroll
    for (int r = 0; r < 32; r += 8) {
        float v = t[tx][ty + r];
        __nv_bfloat16 h = __float2bfloat16(v);
        __nv_bfloat16 l = __float2bfloat16(v - __bfloat162float(h));
        size_t o = (size_t)(bn + ty + r) * K + bk + tx;
        hi[o] = h;
        lo[o] = l;
    }
}

// ---------------------------------------------------------------------------
// Causal flash attention, fp32 (unchanged from passing R3 kernel)
// ---------------------------------------------------------------------------
__global__ __launch_bounds__(128, 2)
void attn_kernel(const float* __restrict__ qkv, float* __restrict__ out) {
    const float scale = 0.125f;
    int tid = threadIdx.x;
    int bh  = blockIdx.y;
    int b   = bh >> 4;
    int h   = bh & 15;
    int row = blockIdx.x * 128 + tid;

    const float* base = qkv + (size_t)b * SEQ_T * N_QKV;

    float q[HS];
    {
        const float* qp = base + (size_t)row * N_QKV + h * HS;
        #pragma unroll
        for (int d = 0; d < HS; d += 4) {
            float4 t4 = *reinterpret_cast<const float4*>(qp + d);
            q[d] = t4.x; q[d + 1] = t4.y; q[d + 2] = t4.z; q[d + 3] = t4.w;
        }
    }

    float m = -1e30f, l = 0.f;
    float acc[HS];
    #pragma unroll
    for (int d = 0; d < HS; d++) acc[d] = 0.f;

    __shared__ float Ks[64][HS];
    __shared__ float Vs[64][HS];

    int kmax = blockIdx.x * 128 + 127;

    for (int k0 = 0; k0 <= kmax; k0 += 64) {
        #pragma unroll
        for (int i = 0; i < 8; i++) {
            int v = tid + i * 128;
            int j = v >> 4;
            int d = (v & 15) * 4;
            const float* kp = base + (size_t)(k0 + j) * N_QKV + N_EMB   + h * HS + d;
            const float* vp = base + (size_t)(k0 + j) * N_QKV + 2*N_EMB + h * HS + d;
            *reinterpret_cast<float4*>(&Ks[j][d]) = *reinterpret_cast<const float4*>(kp);
            *reinterpret_cast<float4*>(&Vs[j][d]) = *reinterpret_cast<const float4*>(vp);
        }
        __syncthreads();

        int jend = row - k0 + 1;
        if (jend > 64) jend = 64;
        for (int j = 0; j < jend; j++) {
            float s = 0.f;
            #pragma unroll
            for (int d = 0; d < HS; d++) s += q[d] * Ks[j][d];
            s *= scale;
            if (s <= m) {
                float p = __expf(s - m);
                l += p;
                #pragma unroll
                for (int d = 0; d < HS; d++) acc[d] += p * Vs[j][d];
            } else {
                float corr = __expf(m - s);
                l = l * corr + 1.f;
                #pragma unroll
                for (int d = 0; d < HS; d++) acc[d] = acc[d] * corr + Vs[j][d];
                m = s;
            }
        }
        __syncthreads();
    }

    float inv = 1.f / l;
    float* op = out + ((size_t)(b * SEQ_T + row)) * N_EMB + h * HS;
    #pragma unroll
    for (int d = 0; d < HS; d += 4) {
        float4 o;
        o.x = acc[d + 0] * inv; o.y = acc[d + 1] * inv;
        o.z = acc[d + 2] * inv; o.w = acc[d + 3] * inv;
        *reinterpret_cast<float4*>(op + d) = o;
    }
}

// ---------------------------------------------------------------------------
// Launch
// ---------------------------------------------------------------------------
extern "C" void kernel_launch(void* const* d_in, const int* in_sizes, int n_in,
                              void* d_out, int out_size) {
    const float* x    = (const float*)d_in[0];
    const float* Wqkv = (const float*)d_in[1];
    const float* bqkv = (const float*)d_in[2];
    const float* Wout = (const float*)d_in[3];
    const float* bout = (const float*)d_in[4];
    float* out = (float*)d_out;

    float *qkv, *attn;
    __nv_bfloat16 *xhi, *xlo, *ahi, *alo, *wqhi, *wqlo, *wohi, *wolo;
    cudaGetSymbolAddress((void**)&qkv,  g_qkv);
    cudaGetSymbolAddress((void**)&attn, g_attn);
    cudaGetSymbolAddress((void**)&xhi,  g_xhi);
    cudaGetSymbolAddress((void**)&xlo,  g_xlo);
    cudaGetSymbolAddress((void**)&ahi,  g_ahi);
    cudaGetSymbolAddress((void**)&alo,  g_alo);
    cudaGetSymbolAddress((void**)&wqhi, g_wqhi);
    cudaGetSymbolAddress((void**)&wqlo, g_wqlo);
    cudaGetSymbolAddress((void**)&wohi, g_wohi);
    cudaGetSymbolAddress((void**)&wolo, g_wolo);

    cudaFuncSetAttribute(gemm_mma, cudaFuncAttributeMaxDynamicSharedMemorySize, G_SMEM);

    int n4 = (M_ROWS * KDIM) / 4;

    // Precompute operands
    split_f32<<<(n4 + 255) / 256, 256>>>(x, xhi, xlo, n4);
    transpose_split<<<dim3(N_QKV / 32, KDIM / 32), dim3(32, 8)>>>(Wqkv, wqhi, wqlo, KDIM, N_QKV);
    transpose_split<<<dim3(N_EMB / 32, KDIM / 32), dim3(32, 8)>>>(Wout, wohi, wolo, KDIM, N_EMB);

    // 1) QKV projection via HMMA
    gemm_mma<<<dim3(N_QKV / 128, M_ROWS / 128), 256, G_SMEM>>>(
        xhi, xlo, wqhi, wqlo, bqkv, qkv, N_QKV);

    // 2) Causal attention (fp32)
    attn_kernel<<<dim3(SEQ_T / 128, 4 * NHEAD), 128>>>(qkv, attn);

    // 3) Output projection via HMMA
    split_f32<<<(n4 + 255) / 256, 256>>>(attn, ahi, alo, n4);
    gemm_mma<<<dim3(N_EMB / 128, M_ROWS / 128), 256, G_SMEM>>>(
        ahi, alo, wohi, wolo, bout, out, N_EMB);
}

// round 8
// speedup vs baseline: 3.3586x; 2.3151x over previous
#include <cuda_runtime.h>
#include <cuda_bf16.h>
#include <cstdint>

// ---------------------------------------------------------------------------
// Attention block on GB300 (sm_103 target — tcgen05 unavailable in harness):
//   x -> QKV GEMM (mma.sync split-bf16) -> flash attention (mma.sync split-bf16)
//   -> out GEMM (mma.sync split-bf16)
// ---------------------------------------------------------------------------

#define M_ROWS 8192
#define N_EMB  1024
#define N_QKV  3072
#define SEQ_T  2048
#define NHEAD  16
#define HS     64
#define KDIM   1024

// Scratch (__device__ globals per allocation-free rule)
__device__ float g_qkv [(size_t)M_ROWS * N_QKV];    // 96 MB
__device__ float g_attn[(size_t)M_ROWS * N_EMB];    // 32 MB
__device__ __nv_bfloat16 g_qkvhi[(size_t)M_ROWS * N_QKV];  // 48 MB
__device__ __nv_bfloat16 g_qkvlo[(size_t)M_ROWS * N_QKV];  // 48 MB
__device__ __nv_bfloat16 g_xhi[(size_t)M_ROWS * KDIM];
__device__ __nv_bfloat16 g_xlo[(size_t)M_ROWS * KDIM];
__device__ __nv_bfloat16 g_ahi[(size_t)M_ROWS * KDIM];
__device__ __nv_bfloat16 g_alo[(size_t)M_ROWS * KDIM];
__device__ __nv_bfloat16 g_wqhi[(size_t)N_QKV * KDIM];  // Wqkv^T split
__device__ __nv_bfloat16 g_wqlo[(size_t)N_QKV * KDIM];
__device__ __nv_bfloat16 g_wohi[(size_t)N_EMB * KDIM];  // Wout^T split
__device__ __nv_bfloat16 g_wolo[(size_t)N_EMB * KDIM];

// ---------------------------------------------------------------------------
// PTX helpers (sm_80-portable subset only: ldmatrix / mma.sync / cp.async)
// ---------------------------------------------------------------------------
__device__ __forceinline__ uint32_t smem_u32(const void* p) {
    uint32_t a;
    asm("{ .reg .u64 t; cvta.to.shared.u64 t, %1; cvt.u32.u64 %0, t; }"
        : "=r"(a) : "l"(p));
    return a;
}
__device__ __forceinline__ uint32_t swz(uint32_t o) { return o ^ ((o >> 3) & 0x70); }

__device__ __forceinline__ void cp16(uint32_t dst, const void* src) {
    asm volatile("cp.async.cg.shared.global [%0], [%1], 16;" :: "r"(dst), "l"(src));
}
__device__ __forceinline__ void cp_commit() {
    asm volatile("cp.async.commit_group;" ::: "memory");
}
__device__ __forceinline__ void cp_wait1() {
    asm volatile("cp.async.wait_group 1;" ::: "memory");
}
__device__ __forceinline__ void cp_wait0() {
    asm volatile("cp.async.wait_group 0;" ::: "memory");
}

__device__ __forceinline__ void ldsm4(uint32_t& r0, uint32_t& r1, uint32_t& r2,
                                      uint32_t& r3, uint32_t addr) {
    asm volatile("ldmatrix.sync.aligned.m8n8.x4.shared.b16 {%0,%1,%2,%3}, [%4];"
                 : "=r"(r0), "=r"(r1), "=r"(r2), "=r"(r3) : "r"(addr));
}
__device__ __forceinline__ void ldsm4t(uint32_t& r0, uint32_t& r1, uint32_t& r2,
                                       uint32_t& r3, uint32_t addr) {
    asm volatile("ldmatrix.sync.aligned.m8n8.x4.trans.shared.b16 {%0,%1,%2,%3}, [%4];"
                 : "=r"(r0), "=r"(r1), "=r"(r2), "=r"(r3) : "r"(addr));
}

__device__ __forceinline__ void mma16816(float* d, uint32_t a0, uint32_t a1,
                                         uint32_t a2, uint32_t a3,
                                         uint32_t b0, uint32_t b1) {
    asm volatile(
        "mma.sync.aligned.m16n8k16.row.col.f32.bf16.bf16.f32 "
        "{%0,%1,%2,%3}, {%4,%5,%6,%7}, {%8,%9}, {%0,%1,%2,%3};"
        : "+f"(d[0]), "+f"(d[1]), "+f"(d[2]), "+f"(d[3])
        : "r"(a0), "r"(a1), "r"(a2), "r"(a3), "r"(b0), "r"(b1));
}

__device__ __forceinline__ uint32_t pack2(__nv_bfloat16 a, __nv_bfloat16 b) {
    __nv_bfloat162 t(a, b);
    return *reinterpret_cast<uint32_t*>(&t);
}
__device__ __forceinline__ uint32_t packbf(float a, float b) {
    __nv_bfloat162 t = __floats2bfloat162_rn(a, b);
    return *reinterpret_cast<uint32_t*>(&t);
}

// ---------------------------------------------------------------------------
// HMMA split-bf16 GEMM:  C[M,N] = (Ahi+Alo)[M,K] @ (Bhi+Blo)[N,K]^T + bias
// ---------------------------------------------------------------------------
#define G_TILE   16384           // one 128x64 bf16 tile (SW128, 128B rows)
#define G_STAGE  (4 * G_TILE)
#define G_SMEM   (2 * G_STAGE)   // 128 KB

__device__ __forceinline__ void load_chunk(
    uint32_t stage, int k0,
    const __nv_bfloat16* __restrict__ Ahi, const __nv_bfloat16* __restrict__ Alo,
    const __nv_bfloat16* __restrict__ Bhi, const __nv_bfloat16* __restrict__ Blo,
    int bm, int bn, int tid) {
    const __nv_bfloat16* bases[4] = {Ahi, Alo, Bhi, Blo};
    #pragma unroll
    for (int tile = 0; tile < 4; tile++) {
        const __nv_bfloat16* base = bases[tile];
        int rowbase = (tile < 2) ? bm : bn;
        #pragma unroll
        for (int j = 0; j < 4; j++) {
            int p = tid + j * 256;
            int row = p >> 3;
            int c16 = p & 7;
            const __nv_bfloat16* src =
                base + (size_t)(rowbase + row) * KDIM + k0 + c16 * 8;
            uint32_t dst = stage + tile * G_TILE + swz(row * 128 + c16 * 16);
            cp16(dst, src);
        }
    }
    cp_commit();
}

__global__ __launch_bounds__(256, 1)
void gemm_mma(const __nv_bfloat16* __restrict__ Ahi, const __nv_bfloat16* __restrict__ Alo,
              const __nv_bfloat16* __restrict__ Bhi, const __nv_bfloat16* __restrict__ Blo,
              const float* __restrict__ bias, float* __restrict__ C, int N) {
    extern __shared__ char smem[];
    uint32_t sb = smem_u32(smem);
    int tid  = threadIdx.x;
    int lane = tid & 31;
    int w    = tid >> 5;
    int bm = blockIdx.y * 128;
    int bn = blockIdx.x * 128;
    int wm = (w >> 2) * 64;
    int wn = (w & 3) * 32;

    float acc[4][4][4];
    #pragma unroll
    for (int i = 0; i < 4; i++)
        #pragma unroll
        for (int j = 0; j < 4; j++)
            #pragma unroll
            for (int r = 0; r < 4; r++) acc[i][j][r] = 0.f;

    uint32_t st[2] = {sb, sb + G_STAGE};

    int a_row = wm + (lane & 15);
    int a_hi8 = (lane >> 4);
    int b_row = wn + (lane & 7) + ((lane >> 4) << 3);
    int b_hi8 = (lane >> 3) & 1;

    load_chunk(st[0], 0,  Ahi, Alo, Bhi, Blo, bm, bn, tid);
    load_chunk(st[1], 64, Ahi, Alo, Bhi, Blo, bm, bn, tid);

    #pragma unroll 1
    for (int c = 0; c < 16; c++) {
        uint32_t stage = st[c & 1];
        if (c < 15) cp_wait1(); else cp_wait0();
        __syncthreads();

        uint32_t tAh = stage;
        uint32_t tAl = stage + G_TILE;
        uint32_t tBh = stage + 2 * G_TILE;
        uint32_t tBl = stage + 3 * G_TILE;

        #pragma unroll
        for (int ks = 0; ks < 4; ks++) {
            uint32_t ah[4][4], al[4][4], bh[2][4], bl[2][4];
            uint32_t ac16 = (uint32_t)(ks * 2 + a_hi8) * 16;
            uint32_t bc16 = (uint32_t)(ks * 2 + b_hi8) * 16;
            #pragma unroll
            for (int mt = 0; mt < 4; mt++) {
                uint32_t off = swz((uint32_t)(a_row + mt * 16) * 128 + ac16);
                ldsm4(ah[mt][0], ah[mt][1], ah[mt][2], ah[mt][3], tAh + off);
                ldsm4(al[mt][0], al[mt][1], al[mt][2], al[mt][3], tAl + off);
            }
            #pragma unroll
            for (int nt = 0; nt < 2; nt++) {
                uint32_t off = swz((uint32_t)(b_row + nt * 16) * 128 + bc16);
                ldsm4(bh[nt][0], bh[nt][1], bh[nt][2], bh[nt][3], tBh + off);
                ldsm4(bl[nt][0], bl[nt][1], bl[nt][2], bl[nt][3], tBl + off);
            }
            #pragma unroll
            for (int mt = 0; mt < 4; mt++) {
                #pragma unroll
                for (int n8 = 0; n8 < 4; n8++) {
                    uint32_t b0h = bh[n8 >> 1][(n8 & 1) * 2];
                    uint32_t b1h = bh[n8 >> 1][(n8 & 1) * 2 + 1];
                    uint32_t b0l = bl[n8 >> 1][(n8 & 1) * 2];
                    uint32_t b1l = bl[n8 >> 1][(n8 & 1) * 2 + 1];
                    mma16816(acc[mt][n8], ah[mt][0], ah[mt][1], ah[mt][2], ah[mt][3], b0h, b1h);
                    mma16816(acc[mt][n8], ah[mt][0], ah[mt][1], ah[mt][2], ah[mt][3], b0l, b1l);
                    mma16816(acc[mt][n8], al[mt][0], al[mt][1], al[mt][2], al[mt][3], b0h, b1h);
                }
            }
        }
        __syncthreads();
        if (c + 2 < 16)
            load_chunk(stage, (c + 2) * 64, Ahi, Alo, Bhi, Blo, bm, bn, tid);
    }

    int tr = lane >> 2;
    int tc = (lane & 3) * 2;
    #pragma unroll
    for (int mt = 0; mt < 4; mt++) {
        #pragma unroll
        for (int n8 = 0; n8 < 4; n8++) {
            int row0 = bm + wm + mt * 16 + tr;
            int col  = bn + wn + n8 * 8 + tc;
            float b0 = bias[col], b1 = bias[col + 1];
            float* p0 = C + (size_t)row0 * N + col;
            p0[0] = acc[mt][n8][0] + b0;
            p0[1] = acc[mt][n8][1] + b1;
            float* p1 = C + (size_t)(row0 + 8) * N + col;
            p1[0] = acc[mt][n8][2] + b0;
            p1[1] = acc[mt][n8][3] + b1;
        }
    }
}

// ---------------------------------------------------------------------------
// fp32 -> bf16 hi/lo split (elementwise, float4)
// ---------------------------------------------------------------------------
__global__ void split_f32(const float* __restrict__ in, __nv_bfloat16* __restrict__ hi,
                          __nv_bfloat16* __restrict__ lo, int n4) {
    int i = blockIdx.x * blockDim.x + threadIdx.x;
    if (i >= n4) return;
    float4 v = reinterpret_cast<const float4*>(in)[i];
    float vv[4] = {v.x, v.y, v.z, v.w};
    __nv_bfloat162 h2[2], l2[2];
    #pragma unroll
    for (int j = 0; j < 4; j++) {
        __nv_bfloat16 h = __float2bfloat16(vv[j]);
        __nv_bfloat16 l = __float2bfloat16(vv[j] - __bfloat162float(h));
        ((__nv_bfloat16*)h2)[j] = h;
        ((__nv_bfloat16*)l2)[j] = l;
    }
    reinterpret_cast<__nv_bfloat162*>(hi)[i * 2 + 0] = h2[0];
    reinterpret_cast<__nv_bfloat162*>(hi)[i * 2 + 1] = h2[1];
    reinterpret_cast<__nv_bfloat162*>(lo)[i * 2 + 0] = l2[0];
    reinterpret_cast<__nv_bfloat162*>(lo)[i * 2 + 1] = l2[1];
}

// ---------------------------------------------------------------------------
// W [K,N] fp32 -> Wt hi/lo [N,K] bf16 (transpose + split)
// ---------------------------------------------------------------------------
__global__ void transpose_split(const float* __restrict__ W, __nv_bfloat16* __restrict__ hi,
                                __nv_bfloat16* __restrict__ lo, int K, int N) {
    __shared__ float t[32][33];
    int bn = blockIdx.x * 32, bk = blockIdx.y * 32;
    int tx = threadIdx.x, ty = threadIdx.y;
    #pragma unroll
    for (int r = 0; r < 32; r += 8)
        t[ty + r][tx] = W[(size_t)(bk + ty + r) * N + bn + tx];
    __syncthreads();
    #pragma unroll
    for (int r = 0; r < 32; r += 8) {
        float v = t[tx][ty + r];
        __nv_bfloat16 h = __float2bfloat16(v);
        __nv_bfloat16 l = __float2bfloat16(v - __bfloat162float(h));
        size_t o = (size_t)(bn + ty + r) * K + bk + tx;
        hi[o] = h;
        lo[o] = l;
    }
}

// ---------------------------------------------------------------------------
// Flash attention via HMMA, split-bf16 both GEMMs, fp32 softmax.
// Block: 256 thr = 8 warps, 128 q rows (16 per warp). Key tiles of 64.
// smem stage (32 KB): Khi@0, Klo@8K, Vhi@16K, Vlo@24K; two stages.
// ---------------------------------------------------------------------------
#define A_STAGE 32768
#define A_SMEM  (2 * A_STAGE)

__device__ __forceinline__ void attn_load_kv(uint32_t stage, int k0,
        const __nv_bfloat16* __restrict__ Bhi, const __nv_bfloat16* __restrict__ Blo,
        int h, int tid) {
    #pragma unroll
    for (int i = 0; i < 2; i++) {
        int p = tid + i * 256;          // 0..511
        int row = p >> 3, c = p & 7;
        size_t gk = (size_t)(k0 + row) * N_QKV +     N_EMB + h * HS + c * 8;
        size_t gv = (size_t)(k0 + row) * N_QKV + 2 * N_EMB + h * HS + c * 8;
        uint32_t so = swz(row * 128 + c * 16);
        cp16(stage + so,         Bhi + gk);
        cp16(stage + 8192 + so,  Blo + gk);
        cp16(stage + 16384 + so, Bhi + gv);
        cp16(stage + 24576 + so, Blo + gv);
    }
    cp_commit();
}

__global__ __launch_bounds__(256, 1)
void attn_mma(const __nv_bfloat16* __restrict__ QKVhi,
              const __nv_bfloat16* __restrict__ QKVlo,
              float* __restrict__ out) {
    extern __shared__ char smem[];
    uint32_t sb = smem_u32(smem);
    int tid = threadIdx.x, lane = tid & 31, w = tid >> 5;
    int qb = blockIdx.x;                // q tile (128 rows)
    int bh = blockIdx.y, b = bh >> 4, h = bh & 15;
    const __nv_bfloat16* Bhi = QKVhi + (size_t)b * SEQ_T * N_QKV;
    const __nv_bfloat16* Blo = QKVlo + (size_t)b * SEQ_T * N_QKV;
    int tr = lane >> 2, tc = lane & 3;
    int wrow0 = qb * 128 + w * 16;      // warp's first q row (seq coord)

    // ---- Stage Q tile (128x64 hi/lo) into smem, extract frags ----
    #pragma unroll
    for (int i = 0; i < 4; i++) {
        int p = tid + i * 256;
        int row = p >> 3, c = p & 7;
        size_t g = (size_t)(qb * 128 + row) * N_QKV + h * HS + c * 8;
        uint32_t so = swz(row * 128 + c * 16);
        cp16(sb + so, Bhi + g);
        cp16(sb + 16384 + so, Blo + g);
    }
    cp_commit(); cp_wait0(); __syncthreads();

    uint32_t qh[4][4], ql[4][4];
    {
        int a_row = w * 16 + (lane & 15);
        int a_hi8 = lane >> 4;
        #pragma unroll
        for (int ks = 0; ks < 4; ks++) {
            uint32_t off = swz((uint32_t)a_row * 128 + (ks * 2 + a_hi8) * 16);
            ldsm4(qh[ks][0], qh[ks][1], qh[ks][2], qh[ks][3], sb + off);
            ldsm4(ql[ks][0], ql[ks][1], ql[ks][2], ql[ks][3], sb + 16384 + off);
        }
    }
    __syncthreads();

    // ---- Main loop over 64-key tiles ----
    float m0 = -1e30f, m1 = -1e30f, l0 = 0.f, l1 = 0.f;
    float o[8][4];
    #pragma unroll
    for (int i = 0; i < 8; i++)
        #pragma unroll
        for (int r = 0; r < 4; r++) o[i][r] = 0.f;

    uint32_t st[2] = {sb, sb + A_STAGE};
    int ntiles = 2 * (qb + 1);
    int wmax = wrow0 + 15;

    attn_load_kv(st[0], 0, Bhi, Blo, h, tid);
    attn_load_kv(st[1], 64, Bhi, Blo, h, tid);

    int b_row = (lane & 7) + ((lane >> 4) << 3);
    int b_hi8 = (lane >> 3) & 1;

    #pragma unroll 1
    for (int t = 0; t < ntiles; t++) {
        int k0 = t * 64;
        uint32_t stage = st[t & 1];
        if (t + 1 < ntiles) cp_wait1(); else cp_wait0();
        __syncthreads();

        if (k0 <= wmax) {   // warp-uniform: skip fully-masked tiles
            // ---- S = Q K^T (3-term split) ----
            float s[8][4];
            #pragma unroll
            for (int i = 0; i < 8; i++)
                #pragma unroll
                for (int r = 0; r < 4; r++) s[i][r] = 0.f;

            #pragma unroll
            for (int ks = 0; ks < 4; ks++) {
                uint32_t kh[4][4], kl[4][4];
                uint32_t bc16 = (uint32_t)(ks * 2 + b_hi8) * 16;
                #pragma unroll
                for (int nt = 0; nt < 4; nt++) {
                    uint32_t off = swz((uint32_t)(b_row + nt * 16) * 128 + bc16);
                    ldsm4(kh[nt][0], kh[nt][1], kh[nt][2], kh[nt][3], stage + off);
                    ldsm4(kl[nt][0], kl[nt][1], kl[nt][2], kl[nt][3], stage + 8192 + off);
                }
                #pragma unroll
                for (int n8 = 0; n8 < 8; n8++) {
                    uint32_t b0h = kh[n8 >> 1][(n8 & 1) * 2];
                    uint32_t b1h = kh[n8 >> 1][(n8 & 1) * 2 + 1];
                    uint32_t b0l = kl[n8 >> 1][(n8 & 1) * 2];
                    uint32_t b1l = kl[n8 >> 1][(n8 & 1) * 2 + 1];
                    mma16816(s[n8], qh[ks][0], qh[ks][1], qh[ks][2], qh[ks][3], b0h, b1h);
                    mma16816(s[n8], qh[ks][0], qh[ks][1], qh[ks][2], qh[ks][3], b0l, b1l);
                    mma16816(s[n8], ql[ks][0], ql[ks][1], ql[ks][2], ql[ks][3], b0h, b1h);
                }
            }

            // ---- scale + causal mask + row max ----
            int row0 = wrow0 + tr, row1 = row0 + 8;
            bool diag = (k0 + 63 > wrow0);
            float mx0 = -1e30f, mx1 = -1e30f;
            #pragma unroll
            for (int n8 = 0; n8 < 8; n8++) {
                #pragma unroll
                for (int r = 0; r < 4; r++) s[n8][r] *= 0.125f;
                if (diag) {
                    int c0 = k0 + n8 * 8 + tc * 2, c1 = c0 + 1;
                    if (c0 > row0) s[n8][0] = -3.0e38f;
                    if (c1 > row0) s[n8][1] = -3.0e38f;
                    if (c0 > row1) s[n8][2] = -3.0e38f;
                    if (c1 > row1) s[n8][3] = -3.0e38f;
                }
                mx0 = fmaxf(mx0, fmaxf(s[n8][0], s[n8][1]));
                mx1 = fmaxf(mx1, fmaxf(s[n8][2], s[n8][3]));
            }
            mx0 = fmaxf(mx0, __shfl_xor_sync(0xffffffffu, mx0, 1));
            mx0 = fmaxf(mx0, __shfl_xor_sync(0xffffffffu, mx0, 2));
            mx1 = fmaxf(mx1, __shfl_xor_sync(0xffffffffu, mx1, 1));
            mx1 = fmaxf(mx1, __shfl_xor_sync(0xffffffffu, mx1, 2));

            float nm0 = fmaxf(m0, mx0), nm1 = fmaxf(m1, mx1);
            float cr0 = __expf(m0 - nm0), cr1 = __expf(m1 - nm1);
            m0 = nm0; m1 = nm1;
            l0 *= cr0; l1 *= cr1;
            #pragma unroll
            for (int n8 = 0; n8 < 8; n8++) {
                o[n8][0] *= cr0; o[n8][1] *= cr0;
                o[n8][2] *= cr1; o[n8][3] *= cr1;
            }

            // ---- P = exp(S - m), pack into A-frags (hi/lo split) ----
            uint32_t ph[4][4], pl[4][4];
            #pragma unroll
            for (int n8 = 0; n8 < 8; n8++) {
                float p0 = __expf(s[n8][0] - nm0);
                float p1 = __expf(s[n8][1] - nm0);
                float p2 = __expf(s[n8][2] - nm1);
                float p3 = __expf(s[n8][3] - nm1);
                l0 += p0 + p1; l1 += p2 + p3;
                __nv_bfloat16 h0 = __float2bfloat16(p0), h1 = __float2bfloat16(p1);
                __nv_bfloat16 h2 = __float2bfloat16(p2), h3 = __float2bfloat16(p3);
                int ks = n8 >> 1, half = (n8 & 1) * 2;
                ph[ks][half]     = pack2(h0, h1);
                ph[ks][half + 1] = pack2(h2, h3);
                pl[ks][half]     = packbf(p0 - __bfloat162float(h0), p1 - __bfloat162float(h1));
                pl[ks][half + 1] = packbf(p2 - __bfloat162float(h2), p3 - __bfloat162float(h3));
            }

            // ---- O += P V (3-term split); V via ldmatrix.trans ----
            #pragma unroll
            for (int ks = 0; ks < 4; ks++) {
                int v_row = ks * 16 + (lane & 7) + ((lane >> 3) & 1) * 8;
                #pragma unroll
                for (int np = 0; np < 4; np++) {
                    int hs0 = np * 16 + (lane >> 4) * 8;
                    uint32_t off = swz((uint32_t)v_row * 128 + hs0 * 2);
                    uint32_t v0, v1, v2, v3, u0, u1, u2, u3;
                    ldsm4t(v0, v1, v2, v3, stage + 16384 + off);
                    ldsm4t(u0, u1, u2, u3, stage + 24576 + off);
                    mma16816(o[np * 2],     ph[ks][0], ph[ks][1], ph[ks][2], ph[ks][3], v0, v1);
                    mma16816(o[np * 2],     ph[ks][0], ph[ks][1], ph[ks][2], ph[ks][3], u0, u1);
                    mma16816(o[np * 2],     pl[ks][0], pl[ks][1], pl[ks][2], pl[ks][3], v0, v1);
                    mma16816(o[np * 2 + 1], ph[ks][0], ph[ks][1], ph[ks][2], ph[ks][3], v2, v3);
                    mma16816(o[np * 2 + 1], ph[ks][0], ph[ks][1], ph[ks][2], ph[ks][3], u2, u3);
                    mma16816(o[np * 2 + 1], pl[ks][0], pl[ks][1], pl[ks][2], pl[ks][3], v2, v3);
                }
            }
        }
        __syncthreads();
        if (t + 2 < ntiles)
            attn_load_kv(stage, (t + 2) * 64, Bhi, Blo, h, tid);
    }

    // ---- finalize: reduce l across quad, normalize, store ----
    l0 += __shfl_xor_sync(0xffffffffu, l0, 1);
    l0 += __shfl_xor_sync(0xffffffffu, l0, 2);
    l1 += __shfl_xor_sync(0xffffffffu, l1, 1);
    l1 += __shfl_xor_sync(0xffffffffu, l1, 2);
    float i0 = 1.f / l0, i1 = 1.f / l1;

    float* p0 = out + (size_t)(b * SEQ_T + wrow0 + tr) * N_EMB + h * HS + tc * 2;
    float* p1 = out + (size_t)(b * SEQ_T + wrow0 + tr + 8) * N_EMB + h * HS + tc * 2;
    #pragma unroll
    for (int n8 = 0; n8 < 8; n8++) {
        float2 a = {o[n8][0] * i0, o[n8][1] * i0};
        float2 c = {o[n8][2] * i1, o[n8][3] * i1};
        *reinterpret_cast<float2*>(p0 + n8 * 8) = a;
        *reinterpret_cast<float2*>(p1 + n8 * 8) = c;
    }
}

// ---------------------------------------------------------------------------
// Launch
// ---------------------------------------------------------------------------
extern "C" void kernel_launch(void* const* d_in, const int* in_sizes, int n_in,
                              void* d_out, int out_size) {
    const float* x    = (const float*)d_in[0];
    const float* Wqkv = (const float*)d_in[1];
    const float* bqkv = (const float*)d_in[2];
    const float* Wout = (const float*)d_in[3];
    const float* bout = (const float*)d_in[4];
    float* out = (float*)d_out;

    float *qkv, *attn;
    __nv_bfloat16 *qkvhi, *qkvlo, *xhi, *xlo, *ahi, *alo, *wqhi, *wqlo, *wohi, *wolo;
    cudaGetSymbolAddress((void**)&qkv,   g_qkv);
    cudaGetSymbolAddress((void**)&attn,  g_attn);
    cudaGetSymbolAddress((void**)&qkvhi, g_qkvhi);
    cudaGetSymbolAddress((void**)&qkvlo, g_qkvlo);
    cudaGetSymbolAddress((void**)&xhi,   g_xhi);
    cudaGetSymbolAddress((void**)&xlo,   g_xlo);
    cudaGetSymbolAddress((void**)&ahi,   g_ahi);
    cudaGetSymbolAddress((void**)&alo,   g_alo);
    cudaGetSymbolAddress((void**)&wqhi,  g_wqhi);
    cudaGetSymbolAddress((void**)&wqlo,  g_wqlo);
    cudaGetSymbolAddress((void**)&wohi,  g_wohi);
    cudaGetSymbolAddress((void**)&wolo,  g_wolo);

    cudaFuncSetAttribute(gemm_mma, cudaFuncAttributeMaxDynamicSharedMemorySize, G_SMEM);
    cudaFuncSetAttribute(attn_mma, cudaFuncAttributeMaxDynamicSharedMemorySize, A_SMEM);

    int n4x = (M_ROWS * KDIM) / 4;
    int n4q = (M_ROWS * N_QKV) / 4;

    // Precompute operands
    split_f32<<<(n4x + 255) / 256, 256>>>(x, xhi, xlo, n4x);
    transpose_split<<<dim3(N_QKV / 32, KDIM / 32), dim3(32, 8)>>>(Wqkv, wqhi, wqlo, KDIM, N_QKV);
    transpose_split<<<dim3(N_EMB / 32, KDIM / 32), dim3(32, 8)>>>(Wout, wohi, wolo, KDIM, N_EMB);

    // 1) QKV projection via HMMA
    gemm_mma<<<dim3(N_QKV / 128, M_ROWS / 128), 256, G_SMEM>>>(
        xhi, xlo, wqhi, wqlo, bqkv, qkv, N_QKV);

    // 2) Split qkv -> hi/lo bf16, then HMMA flash attention
    split_f32<<<(n4q + 255) / 256, 256>>>(qkv, qkvhi, qkvlo, n4q);
    attn_mma<<<dim3(SEQ_T / 128, 4 * NHEAD), 256, A_SMEM>>>(qkvhi, qkvlo, attn);

    // 3) Output projection via HMMA
    split_f32<<<(n4x + 255) / 256, 256>>>(attn, ahi, alo, n4x);
    gemm_mma<<<dim3(N_EMB / 128, M_ROWS / 128), 256, G_SMEM>>>(
        ahi, alo, wohi, wolo, bout, out, N_EMB);
}

// round 9
// speedup vs baseline: 4.2366x; 1.2614x over previous
#include <cuda_runtime.h>
#include <cuda_bf16.h>
#include <cuda_fp16.h>
#include <cstdint>

// ---------------------------------------------------------------------------
// Attention block on GB300 (sm_103 target — tcgen05 unavailable in harness):
//   x -(fp16 2-term HMMA + fused bf16-split epilogue)-> qkv(bf16 hi/lo)
//     -(bf16 3-term HMMA flash attention, fused fp16-split epilogue)-> a(fp16 hi/lo)
//     -(fp16 2-term HMMA)-> out (fp32)
// ---------------------------------------------------------------------------

#define M_ROWS 8192
#define N_EMB  1024
#define N_QKV  3072
#define SEQ_T  2048
#define NHEAD  16
#define HS     64
#define KDIM   1024

// Scratch (__device__ globals per allocation-free rule)
__device__ __nv_bfloat16 g_qkvhi[(size_t)M_ROWS * N_QKV];  // 48 MB
__device__ __nv_bfloat16 g_qkvlo[(size_t)M_ROWS * N_QKV];  // 48 MB
__device__ __half g_xh[(size_t)M_ROWS * KDIM];
__device__ __half g_xl[(size_t)M_ROWS * KDIM];
__device__ __half g_ah[(size_t)M_ROWS * KDIM];   // attention output hi
__device__ __half g_al[(size_t)M_ROWS * KDIM];   // attention output lo
__device__ __half g_wqh[(size_t)N_QKV * KDIM];   // Wqkv^T fp16
__device__ __half g_woh[(size_t)N_EMB * KDIM];   // Wout^T fp16

// ---------------------------------------------------------------------------
// PTX helpers (sm_80-portable subset: ldmatrix / mma.sync / cp.async)
// ---------------------------------------------------------------------------
__device__ __forceinline__ uint32_t smem_u32(const void* p) {
    uint32_t a;
    asm("{ .reg .u64 t; cvta.to.shared.u64 t, %1; cvt.u32.u64 %0, t; }"
        : "=r"(a) : "l"(p));
    return a;
}
__device__ __forceinline__ uint32_t swz(uint32_t o) { return o ^ ((o >> 3) & 0x70); }

__device__ __forceinline__ void cp16(uint32_t dst, const void* src) {
    asm volatile("cp.async.cg.shared.global [%0], [%1], 16;" :: "r"(dst), "l"(src));
}
__device__ __forceinline__ void cp_commit() {
    asm volatile("cp.async.commit_group;" ::: "memory");
}
__device__ __forceinline__ void cp_wait1() {
    asm volatile("cp.async.wait_group 1;" ::: "memory");
}
__device__ __forceinline__ void cp_wait0() {
    asm volatile("cp.async.wait_group 0;" ::: "memory");
}

__device__ __forceinline__ void ldsm4(uint32_t& r0, uint32_t& r1, uint32_t& r2,
                                      uint32_t& r3, uint32_t addr) {
    asm volatile("ldmatrix.sync.aligned.m8n8.x4.shared.b16 {%0,%1,%2,%3}, [%4];"
                 : "=r"(r0), "=r"(r1), "=r"(r2), "=r"(r3) : "r"(addr));
}
__device__ __forceinline__ void ldsm4t(uint32_t& r0, uint32_t& r1, uint32_t& r2,
                                       uint32_t& r3, uint32_t addr) {
    asm volatile("ldmatrix.sync.aligned.m8n8.x4.trans.shared.b16 {%0,%1,%2,%3}, [%4];"
                 : "=r"(r0), "=r"(r1), "=r"(r2), "=r"(r3) : "r"(addr));
}

// bf16 MMA (attention)
__device__ __forceinline__ void mma16816(float* d, uint32_t a0, uint32_t a1,
                                         uint32_t a2, uint32_t a3,
                                         uint32_t b0, uint32_t b1) {
    asm volatile(
        "mma.sync.aligned.m16n8k16.row.col.f32.bf16.bf16.f32 "
        "{%0,%1,%2,%3}, {%4,%5,%6,%7}, {%8,%9}, {%0,%1,%2,%3};"
        : "+f"(d[0]), "+f"(d[1]), "+f"(d[2]), "+f"(d[3])
        : "r"(a0), "r"(a1), "r"(a2), "r"(a3), "r"(b0), "r"(b1));
}
// fp16 MMA (projections)
__device__ __forceinline__ void mma16816h(float* d, uint32_t a0, uint32_t a1,
                                          uint32_t a2, uint32_t a3,
                                          uint32_t b0, uint32_t b1) {
    asm volatile(
        "mma.sync.aligned.m16n8k16.row.col.f32.f16.f16.f32 "
        "{%0,%1,%2,%3}, {%4,%5,%6,%7}, {%8,%9}, {%0,%1,%2,%3};"
        : "+f"(d[0]), "+f"(d[1]), "+f"(d[2]), "+f"(d[3])
        : "r"(a0), "r"(a1), "r"(a2), "r"(a3), "r"(b0), "r"(b1));
}

__device__ __forceinline__ uint32_t pack2(__nv_bfloat16 a, __nv_bfloat16 b) {
    __nv_bfloat162 t(a, b);
    return *reinterpret_cast<uint32_t*>(&t);
}
__device__ __forceinline__ uint32_t packbf(float a, float b) {
    __nv_bfloat162 t = __floats2bfloat162_rn(a, b);
    return *reinterpret_cast<uint32_t*>(&t);
}

// ---------------------------------------------------------------------------
// 2-term fp16 HMMA GEMM: C[M,N] = (Ah+Al)[M,K] @ Bh[N,K]^T + bias
// Tile 128x128, K-chunks of 64, 3-stage cp.async pipeline (load-before-compute)
// mode 0: write fp32 C.  mode 1: write bf16 hi/lo split (Chi, Clo).
// ---------------------------------------------------------------------------
#define G2_TILE  16384                // 128x64 fp16 (SW128, 128B rows)
#define G2_STAGE (3 * G2_TILE)        // Ah, Al, Bh
#define G2_SMEM  (3 * G2_STAGE)       // 147456 B

__device__ __forceinline__ void load_chunk2(
    uint32_t stage, int k0,
    const __half* __restrict__ Ah, const __half* __restrict__ Al,
    const __half* __restrict__ Bh, int bm, int bn, int tid) {
    const __half* bases[3] = {Ah, Al, Bh};
    #pragma unroll
    for (int tile = 0; tile < 3; tile++) {
        const __half* base = bases[tile];
        int rowbase = (tile < 2) ? bm : bn;
        #pragma unroll
        for (int j = 0; j < 4; j++) {
            int p = tid + j * 256;
            int row = p >> 3, c16 = p & 7;
            cp16(stage + tile * G2_TILE + swz(row * 128 + c16 * 16),
                 base + (size_t)(rowbase + row) * KDIM + k0 + c16 * 8);
        }
    }
    cp_commit();
}

__global__ __launch_bounds__(256, 1)
void gemm2_h(const __half* __restrict__ Ah, const __half* __restrict__ Al,
             const __half* __restrict__ Bh, const float* __restrict__ bias,
             float* __restrict__ C32,
             __nv_bfloat16* __restrict__ Chi, __nv_bfloat16* __restrict__ Clo,
             int N, int mode) {
    extern __shared__ char smem[];
    uint32_t sb = smem_u32(smem);
    int tid = threadIdx.x, lane = tid & 31, w = tid >> 5;
    int bm = blockIdx.y * 128;
    int bn = blockIdx.x * 128;
    int wm = (w >> 2) * 64;
    int wn = (w & 3) * 32;

    float acc[4][4][4];
    #pragma unroll
    for (int i = 0; i < 4; i++)
        #pragma unroll
        for (int j = 0; j < 4; j++)
            #pragma unroll
            for (int r = 0; r < 4; r++) acc[i][j][r] = 0.f;

    int a_row = wm + (lane & 15);
    int a_hi8 = lane >> 4;
    int b_row = wn + (lane & 7) + ((lane >> 4) << 3);
    int b_hi8 = (lane >> 3) & 1;

    load_chunk2(sb, 0,  Ah, Al, Bh, bm, bn, tid);
    load_chunk2(sb + G2_STAGE, 64, Ah, Al, Bh, bm, bn, tid);

    #pragma unroll 1
    for (int c = 0; c < 16; c++) {
        uint32_t stage = sb + (uint32_t)(c % 3) * G2_STAGE;
        if (c < 15) cp_wait1(); else cp_wait0();
        __syncthreads();
        if (c + 2 < 16)
            load_chunk2(sb + (uint32_t)((c + 2) % 3) * G2_STAGE, (c + 2) * 64,
                        Ah, Al, Bh, bm, bn, tid);

        uint32_t tAh = stage, tAl = stage + G2_TILE, tBh = stage + 2 * G2_TILE;

        #pragma unroll
        for (int ks = 0; ks < 4; ks++) {
            uint32_t ah[4][4], al[4][4], bh[2][4];
            uint32_t ac16 = (uint32_t)(ks * 2 + a_hi8) * 16;
            uint32_t bc16 = (uint32_t)(ks * 2 + b_hi8) * 16;
            #pragma unroll
            for (int mt = 0; mt < 4; mt++) {
                uint32_t off = swz((uint32_t)(a_row + mt * 16) * 128 + ac16);
                ldsm4(ah[mt][0], ah[mt][1], ah[mt][2], ah[mt][3], tAh + off);
                ldsm4(al[mt][0], al[mt][1], al[mt][2], al[mt][3], tAl + off);
            }
            #pragma unroll
            for (int nt = 0; nt < 2; nt++) {
                uint32_t off = swz((uint32_t)(b_row + nt * 16) * 128 + bc16);
                ldsm4(bh[nt][0], bh[nt][1], bh[nt][2], bh[nt][3], tBh + off);
            }
            #pragma unroll
            for (int mt = 0; mt < 4; mt++) {
                #pragma unroll
                for (int n8 = 0; n8 < 4; n8++) {
                    uint32_t b0 = bh[n8 >> 1][(n8 & 1) * 2];
                    uint32_t b1 = bh[n8 >> 1][(n8 & 1) * 2 + 1];
                    mma16816h(acc[mt][n8], ah[mt][0], ah[mt][1], ah[mt][2], ah[mt][3], b0, b1);
                    mma16816h(acc[mt][n8], al[mt][0], al[mt][1], al[mt][2], al[mt][3], b0, b1);
                }
            }
        }
        // NOTE: no trailing barrier; next-iteration top barrier protects reuse.
    }

    int tr = lane >> 2;
    int tc = (lane & 3) * 2;
    if (mode == 0) {
        #pragma unroll
        for (int mt = 0; mt < 4; mt++) {
            #pragma unroll
            for (int n8 = 0; n8 < 4; n8++) {
                int row0 = bm + wm + mt * 16 + tr;
                int col  = bn + wn + n8 * 8 + tc;
                float b0 = bias[col], b1 = bias[col + 1];
                float* p0 = C32 + (size_t)row0 * N + col;
                p0[0] = acc[mt][n8][0] + b0;
                p0[1] = acc[mt][n8][1] + b1;
                float* p1 = C32 + (size_t)(row0 + 8) * N + col;
                p1[0] = acc[mt][n8][2] + b0;
                p1[1] = acc[mt][n8][3] + b1;
            }
        }
    } else {
        #pragma unroll
        for (int mt = 0; mt < 4; mt++) {
            #pragma unroll
            for (int n8 = 0; n8 < 4; n8++) {
                int row0 = bm + wm + mt * 16 + tr;
                int col  = bn + wn + n8 * 8 + tc;
                float b0 = bias[col], b1 = bias[col + 1];
                float c00 = acc[mt][n8][0] + b0, c01 = acc[mt][n8][1] + b1;
                float c10 = acc[mt][n8][2] + b0, c11 = acc[mt][n8][3] + b1;
                #pragma unroll
                for (int rr = 0; rr < 2; rr++) {
                    float v0 = rr ? c10 : c00, v1 = rr ? c11 : c01;
                    __nv_bfloat16 h0 = __float2bfloat16(v0);
                    __nv_bfloat16 h1 = __float2bfloat16(v1);
                    __nv_bfloat16 l0 = __float2bfloat16(v0 - __bfloat162float(h0));
                    __nv_bfloat16 l1 = __float2bfloat16(v1 - __bfloat162float(h1));
                    size_t o = ((size_t)(row0 + rr * 8) * N + col);
                    *reinterpret_cast<__nv_bfloat162*>(Chi + o) = __nv_bfloat162(h0, h1);
                    *reinterpret_cast<__nv_bfloat162*>(Clo + o) = __nv_bfloat162(l0, l1);
                }
            }
        }
    }
}

// ---------------------------------------------------------------------------
// fp32 -> fp16 hi/lo split (for x)
// ---------------------------------------------------------------------------
__global__ void split_f32_h(const float* __restrict__ in, __half* __restrict__ hi,
                            __half* __restrict__ lo, int n4) {
    int i = blockIdx.x * blockDim.x + threadIdx.x;
    if (i >= n4) return;
    float4 v = reinterpret_cast<const float4*>(in)[i];
    float vv[4] = {v.x, v.y, v.z, v.w};
    __half h[4], l[4];
    #pragma unroll
    for (int j = 0; j < 4; j++) {
        h[j] = __float2half_rn(vv[j]);
        l[j] = __float2half_rn(vv[j] - __half2float(h[j]));
    }
    reinterpret_cast<__half2*>(hi)[i * 2 + 0] = __halves2half2(h[0], h[1]);
    reinterpret_cast<__half2*>(hi)[i * 2 + 1] = __halves2half2(h[2], h[3]);
    reinterpret_cast<__half2*>(lo)[i * 2 + 0] = __halves2half2(l[0], l[1]);
    reinterpret_cast<__half2*>(lo)[i * 2 + 1] = __halves2half2(l[2], l[3]);
}

// ---------------------------------------------------------------------------
// W [K,N] fp32 -> Wt [N,K] fp16 (transpose + convert)
// ---------------------------------------------------------------------------
__global__ void transpose_cvt_h(const float* __restrict__ W, __half* __restrict__ Wt,
                                int K, int N) {
    __shared__ float t[32][33];
    int bn = blockIdx.x * 32, bk = blockIdx.y * 32;
    int tx = threadIdx.x, ty = threadIdx.y;
    #pragma unroll
    for (int r = 0; r < 32; r += 8)
        t[ty + r][tx] = W[(size_t)(bk + ty + r) * N + bn + tx];
    __syncthreads();
    #pragma unroll
    for (int r = 0; r < 32; r += 8)
        Wt[(size_t)(bn + ty + r) * K + bk + tx] = __float2half_rn(t[tx][ty + r]);
}

// ---------------------------------------------------------------------------
// Flash attention via HMMA (bf16 3-term), fp32 softmax, fp16 hi/lo output.
// Block: 256 thr = 8 warps, 128 q rows. Key tiles of 64, 3-stage pipeline.
// Stage (32 KB): Khi@0, Klo@8K, Vhi@16K, Vlo@24K.
// ---------------------------------------------------------------------------
#define A_STAGE 32768
#define A_SMEM  (3 * A_STAGE)        // 98304 B

__device__ __forceinline__ void attn_load_kv(uint32_t stage, int k0,
        const __nv_bfloat16* __restrict__ Bhi, const __nv_bfloat16* __restrict__ Blo,
        int h, int tid) {
    #pragma unroll
    for (int i = 0; i < 2; i++) {
        int p = tid + i * 256;          // 0..511
        int row = p >> 3, c = p & 7;
        size_t gk = (size_t)(k0 + row) * N_QKV +     N_EMB + h * HS + c * 8;
        size_t gv = (size_t)(k0 + row) * N_QKV + 2 * N_EMB + h * HS + c * 8;
        uint32_t so = swz(row * 128 + c * 16);
        cp16(stage + so,         Bhi + gk);
        cp16(stage + 8192 + so,  Blo + gk);
        cp16(stage + 16384 + so, Bhi + gv);
        cp16(stage + 24576 + so, Blo + gv);
    }
    cp_commit();
}

__global__ __launch_bounds__(256, 1)
void attn_mma(const __nv_bfloat16* __restrict__ QKVhi,
              const __nv_bfloat16* __restrict__ QKVlo,
              __half* __restrict__ Ohi, __half* __restrict__ Olo) {
    extern __shared__ char smem[];
    uint32_t sb = smem_u32(smem);
    int tid = threadIdx.x, lane = tid & 31, w = tid >> 5;
    int qb = blockIdx.x;
    int bh = blockIdx.y, b = bh >> 4, h = bh & 15;
    const __nv_bfloat16* Bhi = QKVhi + (size_t)b * SEQ_T * N_QKV;
    const __nv_bfloat16* Blo = QKVlo + (size_t)b * SEQ_T * N_QKV;
    int tr = lane >> 2, tc = lane & 3;
    int wrow0 = qb * 128 + w * 16;

    // ---- Stage Q tile (128x64 hi/lo) into smem, extract frags ----
    #pragma unroll
    for (int i = 0; i < 4; i++) {
        int p = tid + i * 256;
        int row = p >> 3, c = p & 7;
        size_t g = (size_t)(qb * 128 + row) * N_QKV + h * HS + c * 8;
        uint32_t so = swz(row * 128 + c * 16);
        cp16(sb + so, Bhi + g);
        cp16(sb + 16384 + so, Blo + g);
    }
    cp_commit(); cp_wait0(); __syncthreads();

    uint32_t qh[4][4], ql[4][4];
    {
        int a_row = w * 16 + (lane & 15);
        int a_hi8 = lane >> 4;
        #pragma unroll
        for (int ks = 0; ks < 4; ks++) {
            uint32_t off = swz((uint32_t)a_row * 128 + (ks * 2 + a_hi8) * 16);
            ldsm4(qh[ks][0], qh[ks][1], qh[ks][2], qh[ks][3], sb + off);
            ldsm4(ql[ks][0], ql[ks][1], ql[ks][2], ql[ks][3], sb + 16384 + off);
        }
    }
    __syncthreads();

    // ---- Main loop over 64-key tiles (3-stage, load-before-compute) ----
    float m0 = -1e30f, m1 = -1e30f, l0 = 0.f, l1 = 0.f;
    float o[8][4];
    #pragma unroll
    for (int i = 0; i < 8; i++)
        #pragma unroll
        for (int r = 0; r < 4; r++) o[i][r] = 0.f;

    int ntiles = 2 * (qb + 1);
    int wmax = wrow0 + 15;

    attn_load_kv(sb, 0, Bhi, Blo, h, tid);
    if (ntiles > 1) attn_load_kv(sb + A_STAGE, 64, Bhi, Blo, h, tid);
    else cp_commit();   // keep group-count arithmetic uniform

    int b_row = (lane & 7) + ((lane >> 4) << 3);
    int b_hi8 = (lane >> 3) & 1;

    #pragma unroll 1
    for (int t = 0; t < ntiles; t++) {
        int k0 = t * 64;
        uint32_t stage = sb + (uint32_t)(t % 3) * A_STAGE;
        if (t + 1 < ntiles) cp_wait1(); else cp_wait0();
        __syncthreads();
        if (t + 2 < ntiles)
            attn_load_kv(sb + (uint32_t)((t + 2) % 3) * A_STAGE, (t + 2) * 64,
                         Bhi, Blo, h, tid);

        if (k0 <= wmax) {   // warp-uniform: skip fully-masked tiles
            // ---- S = Q K^T (3-term split) ----
            float s[8][4];
            #pragma unroll
            for (int i = 0; i < 8; i++)
                #pragma unroll
                for (int r = 0; r < 4; r++) s[i][r] = 0.f;

            #pragma unroll
            for (int ks = 0; ks < 4; ks++) {
                uint32_t kh[4][4], kl[4][4];
                uint32_t bc16 = (uint32_t)(ks * 2 + b_hi8) * 16;
                #pragma unroll
                for (int nt = 0; nt < 4; nt++) {
                    uint32_t off = swz((uint32_t)(b_row + nt * 16) * 128 + bc16);
                    ldsm4(kh[nt][0], kh[nt][1], kh[nt][2], kh[nt][3], stage + off);
                    ldsm4(kl[nt][0], kl[nt][1], kl[nt][2], kl[nt][3], stage + 8192 + off);
                }
                #pragma unroll
                for (int n8 = 0; n8 < 8; n8++) {
                    uint32_t b0h = kh[n8 >> 1][(n8 & 1) * 2];
                    uint32_t b1h = kh[n8 >> 1][(n8 & 1) * 2 + 1];
                    uint32_t b0l = kl[n8 >> 1][(n8 & 1) * 2];
                    uint32_t b1l = kl[n8 >> 1][(n8 & 1) * 2 + 1];
                    mma16816(s[n8], qh[ks][0], qh[ks][1], qh[ks][2], qh[ks][3], b0h, b1h);
                    mma16816(s[n8], qh[ks][0], qh[ks][1], qh[ks][2], qh[ks][3], b0l, b1l);
                    mma16816(s[n8], ql[ks][0], ql[ks][1], ql[ks][2], ql[ks][3], b0h, b1h);
                }
            }

            // ---- scale + causal mask + row max ----
            int row0 = wrow0 + tr, row1 = row0 + 8;
            bool diag = (k0 + 63 > wrow0);
            float mx0 = -1e30f, mx1 = -1e30f;
            #pragma unroll
            for (int n8 = 0; n8 < 8; n8++) {
                #pragma unroll
                for (int r = 0; r < 4; r++) s[n8][r] *= 0.125f;
                if (diag) {
                    int c0 = k0 + n8 * 8 + tc * 2, c1 = c0 + 1;
                    if (c0 > row0) s[n8][0] = -3.0e38f;
                    if (c1 > row0) s[n8][1] = -3.0e38f;
                    if (c0 > row1) s[n8][2] = -3.0e38f;
                    if (c1 > row1) s[n8][3] = -3.0e38f;
                }
                mx0 = fmaxf(mx0, fmaxf(s[n8][0], s[n8][1]));
                mx1 = fmaxf(mx1, fmaxf(s[n8][2], s[n8][3]));
            }
            mx0 = fmaxf(mx0, __shfl_xor_sync(0xffffffffu, mx0, 1));
            mx0 = fmaxf(mx0, __shfl_xor_sync(0xffffffffu, mx0, 2));
            mx1 = fmaxf(mx1, __shfl_xor_sync(0xffffffffu, mx1, 1));
            mx1 = fmaxf(mx1, __shfl_xor_sync(0xffffffffu, mx1, 2));

            float nm0 = fmaxf(m0, mx0), nm1 = fmaxf(m1, mx1);
            float cr0 = __expf(m0 - nm0), cr1 = __expf(m1 - nm1);
            m0 = nm0; m1 = nm1;
            l0 *= cr0; l1 *= cr1;
            #pragma unroll
            for (int n8 = 0; n8 < 8; n8++) {
                o[n8][0] *= cr0; o[n8][1] *= cr0;
                o[n8][2] *= cr1; o[n8][3] *= cr1;
            }

            // ---- P = exp(S - m), pack into A-frags (hi/lo split) ----
            uint32_t ph[4][4], pl[4][4];
            #pragma unroll
            for (int n8 = 0; n8 < 8; n8++) {
                float p0 = __expf(s[n8][0] - nm0);
                float p1 = __expf(s[n8][1] - nm0);
                float p2 = __expf(s[n8][2] - nm1);
                float p3 = __expf(s[n8][3] - nm1);
                l0 += p0 + p1; l1 += p2 + p3;
                __nv_bfloat16 h0 = __float2bfloat16(p0), h1 = __float2bfloat16(p1);
                __nv_bfloat16 h2 = __float2bfloat16(p2), h3 = __float2bfloat16(p3);
                int ks = n8 >> 1, half = (n8 & 1) * 2;
                ph[ks][half]     = pack2(h0, h1);
                ph[ks][half + 1] = pack2(h2, h3);
                pl[ks][half]     = packbf(p0 - __bfloat162float(h0), p1 - __bfloat162float(h1));
                pl[ks][half + 1] = packbf(p2 - __bfloat162float(h2), p3 - __bfloat162float(h3));
            }

            // ---- O += P V (3-term split); V via ldmatrix.trans ----
            #pragma unroll
            for (int ks = 0; ks < 4; ks++) {
                int v_row = ks * 16 + (lane & 7) + ((lane >> 3) & 1) * 8;
                #pragma unroll
                for (int np = 0; np < 4; np++) {
                    int hs0 = np * 16 + (lane >> 4) * 8;
                    uint32_t off = swz((uint32_t)v_row * 128 + hs0 * 2);
                    uint32_t v0, v1, v2, v3, u0, u1, u2, u3;
                    ldsm4t(v0, v1, v2, v3, stage + 16384 + off);
                    ldsm4t(u0, u1, u2, u3, stage + 24576 + off);
                    mma16816(o[np * 2],     ph[ks][0], ph[ks][1], ph[ks][2], ph[ks][3], v0, v1);
                    mma16816(o[np * 2],     ph[ks][0], ph[ks][1], ph[ks][2], ph[ks][3], u0, u1);
                    mma16816(o[np * 2],     pl[ks][0], pl[ks][1], pl[ks][2], pl[ks][3], v0, v1);
                    mma16816(o[np * 2 + 1], ph[ks][0], ph[ks][1], ph[ks][2], ph[ks][3], v2, v3);
                    mma16816(o[np * 2 + 1], ph[ks][0], ph[ks][1], ph[ks][2], ph[ks][3], u2, u3);
                    mma16816(o[np * 2 + 1], pl[ks][0], pl[ks][1], pl[ks][2], pl[ks][3], v2, v3);
                }
            }
        }
    }

    // ---- finalize: reduce l, normalize, write fp16 hi/lo ----
    l0 += __shfl_xor_sync(0xffffffffu, l0, 1);
    l0 += __shfl_xor_sync(0xffffffffu, l0, 2);
    l1 += __shfl_xor_sync(0xffffffffu, l1, 1);
    l1 += __shfl_xor_sync(0xffffffffu, l1, 2);
    float i0 = 1.f / l0, i1 = 1.f / l1;

    size_t o0 = (size_t)(b * SEQ_T + wrow0 + tr) * N_EMB + h * HS + tc * 2;
    size_t o1 = (size_t)(b * SEQ_T + wrow0 + tr + 8) * N_EMB + h * HS + tc * 2;
    #pragma unroll
    for (int n8 = 0; n8 < 8; n8++) {
        float v0 = o[n8][0] * i0, v1 = o[n8][1] * i0;
        float v2 = o[n8][2] * i1, v3 = o[n8][3] * i1;
        __half h0 = __float2half_rn(v0), h1 = __float2half_rn(v1);
        __half h2 = __float2half_rn(v2), h3 = __float2half_rn(v3);
        __half e0 = __float2half_rn(v0 - __half2float(h0));
        __half e1 = __float2half_rn(v1 - __half2float(h1));
        __half e2 = __float2half_rn(v2 - __half2float(h2));
        __half e3 = __float2half_rn(v3 - __half2float(h3));
        *reinterpret_cast<__half2*>(Ohi + o0 + n8 * 8) = __halves2half2(h0, h1);
        *reinterpret_cast<__half2*>(Olo + o0 + n8 * 8) = __halves2half2(e0, e1);
        *reinterpret_cast<__half2*>(Ohi + o1 + n8 * 8) = __halves2half2(h2, h3);
        *reinterpret_cast<__half2*>(Olo + o1 + n8 * 8) = __halves2half2(e2, e3);
    }
}

// ---------------------------------------------------------------------------
// Launch
// ---------------------------------------------------------------------------
extern "C" void kernel_launch(void* const* d_in, const int* in_sizes, int n_in,
                              void* d_out, int out_size) {
    const float* x    = (const float*)d_in[0];
    const float* Wqkv = (const float*)d_in[1];
    const float* bqkv = (const float*)d_in[2];
    const float* Wout = (const float*)d_in[3];
    const float* bout = (const float*)d_in[4];
    float* out = (float*)d_out;

    __nv_bfloat16 *qkvhi, *qkvlo;
    __half *xh, *xl, *ah, *al, *wqh, *woh;
    cudaGetSymbolAddress((void**)&qkvhi, g_qkvhi);
    cudaGetSymbolAddress((void**)&qkvlo, g_qkvlo);
    cudaGetSymbolAddress((void**)&xh,  g_xh);
    cudaGetSymbolAddress((void**)&xl,  g_xl);
    cudaGetSymbolAddress((void**)&ah,  g_ah);
    cudaGetSymbolAddress((void**)&al,  g_al);
    cudaGetSymbolAddress((void**)&wqh, g_wqh);
    cudaGetSymbolAddress((void**)&woh, g_woh);

    cudaFuncSetAttribute(gemm2_h, cudaFuncAttributeMaxDynamicSharedMemorySize, G2_SMEM);
    cudaFuncSetAttribute(attn_mma, cudaFuncAttributeMaxDynamicSharedMemorySize, A_SMEM);

    int n4x = (M_ROWS * KDIM) / 4;

    // Precompute operands
    split_f32_h<<<(n4x + 255) / 256, 256>>>(x, xh, xl, n4x);
    transpose_cvt_h<<<dim3(N_QKV / 32, KDIM / 32), dim3(32, 8)>>>(Wqkv, wqh, KDIM, N_QKV);
    transpose_cvt_h<<<dim3(N_EMB / 32, KDIM / 32), dim3(32, 8)>>>(Wout, woh, KDIM, N_EMB);

    // 1) QKV projection (fp16 2-term), fused bf16 hi/lo split epilogue
    gemm2_h<<<dim3(N_QKV / 128, M_ROWS / 128), 256, G2_SMEM>>>(
        xh, xl, wqh, bqkv, nullptr, qkvhi, qkvlo, N_QKV, 1);

    // 2) Flash attention (bf16 3-term), fused fp16 hi/lo split epilogue
    attn_mma<<<dim3(SEQ_T / 128, 4 * NHEAD), 256, A_SMEM>>>(qkvhi, qkvlo, ah, al);

    // 3) Output projection (fp16 2-term) -> fp32 out
    gemm2_h<<<dim3(N_EMB / 128, M_ROWS / 128), 256, G2_SMEM>>>(
        ah, al, woh, bout, out, nullptr, nullptr, N_EMB, 0);
}